// round 8
// baseline (speedup 1.0000x reference)
#include <cuda_runtime.h>
#include <cuda_fp16.h>

#define TSEQ 1024
#define BATCH 4096

__device__ __forceinline__ unsigned tanh2u(unsigned x) {
    unsigned y; asm("tanh.approx.f16x2 %0, %1;" : "=r"(y) : "r"(x)); return y;
}
// pack (lo, hi) floats -> f16x2 (first PTX operand goes to upper half)
__device__ __forceinline__ unsigned cvtpack(float lo, float hi) {
    unsigned d; asm("cvt.rn.f16x2.f32 %0, %1, %2;" : "=r"(d) : "f"(hi), "f"(lo));
    return d;
}
__device__ __forceinline__ __half2 u2h(unsigned u) { return *reinterpret_cast<__half2*>(&u); }
__device__ __forceinline__ unsigned h2u(__half2 h) { return *reinterpret_cast<unsigned*>(&h); }

__device__ __forceinline__ unsigned long long pack2f(float lo, float hi) {
    unsigned long long r;
    asm("mov.b64 %0, {%1, %2};" : "=l"(r) : "f"(lo), "f"(hi)); return r;
}
__device__ __forceinline__ void unpack2f(unsigned long long v, float& lo, float& hi) {
    asm("mov.b64 {%0, %1}, %2;" : "=f"(lo), "=f"(hi) : "l"(v));
}
__device__ __forceinline__ unsigned long long fma2(unsigned long long a,
                                                   unsigned long long b,
                                                   unsigned long long c) {
    unsigned long long d;
    asm("fma.rn.f32x2 %0, %1, %2, %3;" : "=l"(d) : "l"(a), "l"(b), "l"(c));
    return d;
}

__global__ __launch_bounds__(128, 1)
void reac_kernel(
    const float* __restrict__ u,    const float* __restrict__ xz0,
    const float* __restrict__ r1W0, const float* __restrict__ r1b0,
    const float* __restrict__ r1W1, const float* __restrict__ r1b1,
    const float* __restrict__ r1W2, const float* __restrict__ r1b2,
    const float* __restrict__ r2W0, const float* __restrict__ r2b0,
    const float* __restrict__ r2W1, const float* __restrict__ r2b1,
    const float* __restrict__ r2W2, const float* __restrict__ r2b2,
    const float* __restrict__ ymean, const float* __restrict__ ystd,
    const float* __restrict__ umean, const float* __restrict__ ustd,
    float* __restrict__ out)
{
    const int tid = threadIdx.x;
    const int g  = tid & 3;                       // lane within 4-lane group
    const int g4 = g * 4;
    const int e  = blockIdx.x * 32 + (tid >> 2);  // batch element

    // Layer-0 constants for BOTH MLPs, full 16 units, packed f32x2.
    // Every lane computes all 16 pre-activations locally (no broadcast shfl).
    unsigned long long w0aP[8], b0aP[8], w0b0P[8], w0b1P[8], b0bP[8];
    #pragma unroll
    for (int m = 0; m < 8; m++) {
        w0aP[m]  = pack2f(r1W0[2 * m],      r1W0[2 * m + 1]);
        b0aP[m]  = pack2f(r1b0[2 * m],      r1b0[2 * m + 1]);
        w0b0P[m] = pack2f(r2W0[2 * m],      r2W0[2 * m + 1]);
        w0b1P[m] = pack2f(r2W0[16 + 2 * m], r2W0[16 + 2 * m + 1]);
        b0bP[m]  = pack2f(r2b0[2 * m],      r2b0[2 * m + 1]);
    }

    // Register-resident W1 slices (fp16): lane g holds all 16 rows x its 4
    // cols for both MLPs, as half2 (cols 4g,4g+1) and (4g+2,4g+3).
    __half2 wA01[16], wA23[16], wB01[16], wB23[16];
    #pragma unroll
    for (int i = 0; i < 16; i++) {
        wA01[i] = __floats2half2_rn(r1W1[i * 16 + g4 + 0], r1W1[i * 16 + g4 + 1]);
        wA23[i] = __floats2half2_rn(r1W1[i * 16 + g4 + 2], r1W1[i * 16 + g4 + 3]);
        wB01[i] = __floats2half2_rn(r2W1[i * 16 + g4 + 0], r2W1[i * 16 + g4 + 1]);
        wB23[i] = __floats2half2_rn(r2W1[i * 16 + g4 + 2], r2W1[i * 16 + g4 + 3]);
    }

    float w2a[4], w2b[4];
    #pragma unroll
    for (int jj = 0; jj < 4; jj++) { w2a[jj] = r1W2[g4 + jj]; w2b[jj] = r2W2[g4 + jj]; }
    const float basea = 0.25f * r1b2[0], baseb = 0.25f * r2b2[0];
    const __half2 b1a01 = __floats2half2_rn(r1b1[g4 + 0], r1b1[g4 + 1]);
    const __half2 b1a23 = __floats2half2_rn(r1b1[g4 + 2], r1b1[g4 + 3]);
    const __half2 b1b01 = __floats2half2_rn(r2b1[g4 + 0], r2b1[g4 + 1]);
    const __half2 b1b23 = __floats2half2_rn(r2b1[g4 + 2], r2b1[g4 + 3]);
    const __half2 hzero = __floats2half2_rn(0.0f, 0.0f);

    const float Castd = ystd[0], Cbstd = ystd[1];
    const float Camean = ymean[0], Cbmean = ymean[1];
    const float us = ustd[0], um = umean[0];
    // Normalized-coordinate dynamics:
    //   dCa = uc - 0.1*Ca - f1,  uc = ku*u + kc
    //   dCb = kb - 0.1*Cb + kr*f1 - 3*f2
    //   dCc = kb - 0.1*Cc + f2
    const float ku = 0.1f * us / Castd;
    const float kc = 0.1f * (um - Camean) / Castd;
    const float kb = -0.1f * Cbmean / Cbstd;
    const float kr = Castd / Cbstd;

    float x0 = xz0[e * 3 + 0], x1 = xz0[e * 3 + 1], x2 = xz0[e * 3 + 2];
    const float* ue = u + (size_t)e * TSEQ;
    float2* ybase = (float2*)(out + (size_t)e * TSEQ * 2);
    float* xbase = out + (size_t)BATCH * TSEQ * 2 + (size_t)e * TSEQ * 3;

    float uc = 0.0f;

    auto fxu = [&](float c0, float c1, float c2, float& d0, float& d1, float& d2) {
        // layer 0 (packed fp32 FFMA2) -> f16x2 tanh, all 16 units per lane
        const unsigned long long c0p = pack2f(c0, c0);
        const unsigned long long c1p = pack2f(c1, c1);
        const unsigned long long c2p = pack2f(c2, c2);
        __half2 hA[8], hB[8];
        #pragma unroll
        for (int m = 0; m < 8; m++) {
            float lo, hi;
            unpack2f(fma2(c0p, w0aP[m], b0aP[m]), lo, hi);
            hA[m] = u2h(tanh2u(cvtpack(lo, hi)));
            unpack2f(fma2(c2p, w0b1P[m], fma2(c1p, w0b0P[m], b0bP[m])), lo, hi);
            hB[m] = u2h(tanh2u(cvtpack(lo, hi)));
        }
        // layer 1: HFMA2 matvec, all operands in registers, 4-way split accs
        __half2 aA01[4] = { b1a01, hzero, hzero, hzero };
        __half2 aA23[4] = { b1a23, hzero, hzero, hzero };
        __half2 aB01[4] = { b1b01, hzero, hzero, hzero };
        __half2 aB23[4] = { b1b23, hzero, hzero, hzero };
        #pragma unroll
        for (int m = 0; m < 8; m++) {
            const int i0 = 2 * m, i1 = 2 * m + 1;
            const int c0i = i0 & 3, c1i = i1 & 3;
            const __half2 hAl = __low2half2(hA[m]),  hAh = __high2half2(hA[m]);
            const __half2 hBl = __low2half2(hB[m]),  hBh = __high2half2(hB[m]);
            aA01[c0i] = __hfma2(hAl, wA01[i0], aA01[c0i]);
            aA23[c0i] = __hfma2(hAl, wA23[i0], aA23[c0i]);
            aA01[c1i] = __hfma2(hAh, wA01[i1], aA01[c1i]);
            aA23[c1i] = __hfma2(hAh, wA23[i1], aA23[c1i]);
            aB01[c0i] = __hfma2(hBl, wB01[i0], aB01[c0i]);
            aB23[c0i] = __hfma2(hBl, wB23[i0], aB23[c0i]);
            aB01[c1i] = __hfma2(hBh, wB01[i1], aB01[c1i]);
            aB23[c1i] = __hfma2(hBh, wB23[i1], aB23[c1i]);
        }
        const __half2 sA01 = __hadd2(__hadd2(aA01[0], aA01[1]), __hadd2(aA01[2], aA01[3]));
        const __half2 sA23 = __hadd2(__hadd2(aA23[0], aA23[1]), __hadd2(aA23[2], aA23[3]));
        const __half2 sB01 = __hadd2(__hadd2(aB01[0], aB01[1]), __hadd2(aB01[2], aB01[3]));
        const __half2 sB23 = __hadd2(__hadd2(aB23[0], aB23[1]), __hadd2(aB23[2], aB23[3]));
        // layer 2: f16x2 tanh, fp32 dot with w2, quad reduction
        const float2 tA01 = __half22float2(u2h(tanh2u(h2u(sA01))));
        const float2 tA23 = __half22float2(u2h(tanh2u(h2u(sA23))));
        const float2 tB01 = __half22float2(u2h(tanh2u(h2u(sB01))));
        const float2 tB23 = __half22float2(u2h(tanh2u(h2u(sB23))));
        float pA = fmaf(tA01.x, w2a[0], basea);
        float pB = tA01.y * w2a[1];
        float qA = fmaf(tB01.x, w2b[0], baseb);
        float qB = tB01.y * w2b[1];
        pA = fmaf(tA23.x, w2a[2], pA);
        pB = fmaf(tA23.y, w2a[3], pB);
        qA = fmaf(tB23.x, w2b[2], qA);
        qB = fmaf(tB23.y, w2b[3], qB);
        float p1 = pA + pB, p2 = qA + qB;
        p1 += __shfl_xor_sync(0xffffffffu, p1, 1, 4);
        p2 += __shfl_xor_sync(0xffffffffu, p2, 1, 4);
        p1 += __shfl_xor_sync(0xffffffffu, p1, 2, 4);
        p2 += __shfl_xor_sync(0xffffffffu, p2, 2, 4);
        d0 = fmaf(-0.1f, c0, uc) - p1;
        d1 = fmaf(kr, p1, fmaf(-3.0f, p2, fmaf(-0.1f, c1, kb)));
        d2 = fmaf(-0.1f, c2, kb) + p2;
    };

    float ucur = __ldg(&ue[0]);

    #pragma unroll 1
    for (int t = 0; t < TSEQ; t++) {
        // Emit pre-update state (scan collects x_t before the step).
        if (g == 0)      ybase[t] = make_float2(x0, x1);
        else if (g == 1) xbase[t * 3 + 0] = x0;
        else if (g == 2) xbase[t * 3 + 1] = x1;
        else             xbase[t * 3 + 2] = x2;

        uc = fmaf(ku, ucur, kc);
        if (t + 1 < TSEQ) ucur = __ldg(&ue[t + 1]);   // prefetch next step

        float a0, a1, a2, d0, d1, d2, s0, s1, s2;
        fxu(x0, x1, x2, a0, a1, a2);                               // k1
        s0 = fmaf(0.5f, a0, x0); s1 = fmaf(0.5f, a1, x1); s2 = fmaf(0.5f, a2, x2);
        fxu(s0, s1, s2, d0, d1, d2);                               // k2
        a0 = fmaf(2.0f, d0, a0); a1 = fmaf(2.0f, d1, a1); a2 = fmaf(2.0f, d2, a2);
        s0 = fmaf(0.5f, d0, x0); s1 = fmaf(0.5f, d1, x1); s2 = fmaf(0.5f, d2, x2);
        fxu(s0, s1, s2, d0, d1, d2);                               // k3
        a0 = fmaf(2.0f, d0, a0); a1 = fmaf(2.0f, d1, a1); a2 = fmaf(2.0f, d2, a2);
        s0 = x0 + d0; s1 = x1 + d1; s2 = x2 + d2;
        fxu(s0, s1, s2, d0, d1, d2);                               // k4
        a0 += d0; a1 += d1; a2 += d2;
        const float c6 = 1.0f / 6.0f;
        x0 = fmaf(c6, a0, x0); x1 = fmaf(c6, a1, x1); x2 = fmaf(c6, a2, x2);
    }
}

extern "C" void kernel_launch(void* const* d_in, const int* in_sizes, int n_in,
                              void* d_out, int out_size) {
    (void)in_sizes; (void)n_in; (void)out_size;
    reac_kernel<<<128, 128>>>(
        (const float*)d_in[0],  (const float*)d_in[1],
        (const float*)d_in[2],  (const float*)d_in[3],
        (const float*)d_in[4],  (const float*)d_in[5],
        (const float*)d_in[6],  (const float*)d_in[7],
        (const float*)d_in[8],  (const float*)d_in[9],
        (const float*)d_in[10], (const float*)d_in[11],
        (const float*)d_in[12], (const float*)d_in[13],
        (const float*)d_in[14], (const float*)d_in[15],
        (const float*)d_in[16], (const float*)d_in[17],
        (float*)d_out);
}

// round 10
// speedup vs baseline: 1.2773x; 1.2773x over previous
#include <cuda_runtime.h>
#include <cuda_fp16.h>

#define TSEQ 1024
#define BATCH 4096

__device__ __forceinline__ unsigned tanh2u(unsigned x) {
    unsigned y; asm("tanh.approx.f16x2 %0, %1;" : "=r"(y) : "r"(x)); return y;
}
// pack (lo, hi) floats -> f16x2 (first PTX operand goes to upper half)
__device__ __forceinline__ unsigned cvtpack(float lo, float hi) {
    unsigned d; asm("cvt.rn.f16x2.f32 %0, %1, %2;" : "=r"(d) : "f"(hi), "f"(lo));
    return d;
}
__device__ __forceinline__ __half2 u2h(unsigned u) { return *reinterpret_cast<__half2*>(&u); }
__device__ __forceinline__ unsigned h2u(__half2 h) { return *reinterpret_cast<unsigned*>(&h); }

__global__ __launch_bounds__(128, 1)
void reac_kernel(
    const float* __restrict__ u,    const float* __restrict__ xz0,
    const float* __restrict__ r1W0, const float* __restrict__ r1b0,
    const float* __restrict__ r1W1, const float* __restrict__ r1b1,
    const float* __restrict__ r1W2, const float* __restrict__ r1b2,
    const float* __restrict__ r2W0, const float* __restrict__ r2b0,
    const float* __restrict__ r2W1, const float* __restrict__ r2b1,
    const float* __restrict__ r2W2, const float* __restrict__ r2b2,
    const float* __restrict__ ymean, const float* __restrict__ ystd,
    const float* __restrict__ umean, const float* __restrict__ ustd,
    float* __restrict__ out)
{
    const int tid = threadIdx.x;
    const int g  = tid & 3;                       // lane within 4-lane group
    const int g4 = g * 4;
    const int e  = blockIdx.x * 32 + (tid >> 2);  // batch element

    // Register-resident W1 slices (fp16): lane g holds all 16 rows x its 4
    // cols for both MLPs, as half2 (cols 4g,4g+1) and (4g+2,4g+3).
    __half2 wA01[16], wA23[16], wB01[16], wB23[16];
    #pragma unroll
    for (int i = 0; i < 16; i++) {
        wA01[i] = __floats2half2_rn(r1W1[i * 16 + g4 + 0], r1W1[i * 16 + g4 + 1]);
        wA23[i] = __floats2half2_rn(r1W1[i * 16 + g4 + 2], r1W1[i * 16 + g4 + 3]);
        wB01[i] = __floats2half2_rn(r2W1[i * 16 + g4 + 0], r2W1[i * 16 + g4 + 1]);
        wB23[i] = __floats2half2_rn(r2W1[i * 16 + g4 + 2], r2W1[i * 16 + g4 + 3]);
    }

    // Per-lane weight slices: lane g owns hidden units j in [4g, 4g+4).
    float w0a[4], b0a[4], w2a[4];
    float w0b0[4], w0b1[4], b0b[4], w2b[4];
    #pragma unroll
    for (int jj = 0; jj < 4; jj++) {
        const int j = g4 + jj;
        w0a[jj]  = r1W0[j];       b0a[jj] = r1b0[j];
        w0b0[jj] = r2W0[j];       w0b1[jj] = r2W0[16 + j];
        b0b[jj]  = r2b0[j];
        w2a[jj]  = r1W2[j];       w2b[jj] = r2W2[j];
    }
    const float basea = 0.25f * r1b2[0], baseb = 0.25f * r2b2[0];
    const __half2 b1a01 = __floats2half2_rn(r1b1[g4 + 0], r1b1[g4 + 1]);
    const __half2 b1a23 = __floats2half2_rn(r1b1[g4 + 2], r1b1[g4 + 3]);
    const __half2 b1b01 = __floats2half2_rn(r2b1[g4 + 0], r2b1[g4 + 1]);
    const __half2 b1b23 = __floats2half2_rn(r2b1[g4 + 2], r2b1[g4 + 3]);
    const __half2 hzero = __floats2half2_rn(0.0f, 0.0f);

    const float Castd = ystd[0], Cbstd = ystd[1];
    const float Camean = ymean[0], Cbmean = ymean[1];
    const float us = ustd[0], um = umean[0];
    // Normalized-coordinate dynamics:
    //   dCa = uc - 0.1*Ca - f1,  uc = ku*u + kc
    //   dCb = kb - 0.1*Cb + kr*f1 - 3*f2
    //   dCc = kb - 0.1*Cc + f2
    const float ku = 0.1f * us / Castd;
    const float kc = 0.1f * (um - Camean) / Castd;
    const float kb = -0.1f * Cbmean / Cbstd;
    const float kr = Castd / Cbstd;

    float x0 = xz0[e * 3 + 0], x1 = xz0[e * 3 + 1], x2 = xz0[e * 3 + 2];
    const float* ue = u + (size_t)e * TSEQ;
    float2* ybase = (float2*)(out + (size_t)e * TSEQ * 2);
    float* xbase = out + (size_t)BATCH * TSEQ * 2 + (size_t)e * TSEQ * 3;

    float uc = 0.0f;

    auto fxu = [&](float c0, float c1, float c2, float& d0, float& d1, float& d2) {
        // layer 0 (fp32 FMA) -> pack -> hardware f16x2 tanh
        const float pa0 = fmaf(c0, w0a[0], b0a[0]);
        const float pa1 = fmaf(c0, w0a[1], b0a[1]);
        const float pa2 = fmaf(c0, w0a[2], b0a[2]);
        const float pa3 = fmaf(c0, w0a[3], b0a[3]);
        const float pb0 = fmaf(c2, w0b1[0], fmaf(c1, w0b0[0], b0b[0]));
        const float pb1 = fmaf(c2, w0b1[1], fmaf(c1, w0b0[1], b0b[1]));
        const float pb2 = fmaf(c2, w0b1[2], fmaf(c1, w0b0[2], b0b[2]));
        const float pb3 = fmaf(c2, w0b1[3], fmaf(c1, w0b0[3], b0b[3]));
        const unsigned hA0 = tanh2u(cvtpack(pa0, pa1));
        const unsigned hA1 = tanh2u(cvtpack(pa2, pa3));
        const unsigned hB0 = tanh2u(cvtpack(pb0, pb1));
        const unsigned hB1 = tanh2u(cvtpack(pb2, pb3));

        // layer 1: HFMA2 matvec, weights in registers, h via half2 shfl.
        // 4-way split accumulators (one per s): dependent depth 4, tree sum.
        __half2 aA01[4] = { b1a01, hzero, hzero, hzero };
        __half2 aA23[4] = { b1a23, hzero, hzero, hzero };
        __half2 aB01[4] = { b1b01, hzero, hzero, hzero };
        __half2 aB23[4] = { b1b23, hzero, hzero, hzero };
        #pragma unroll
        for (int s = 0; s < 4; s++) {
            const __half2 vA0 = u2h(__shfl_sync(0xffffffffu, hA0, s, 4));
            const __half2 vA1 = u2h(__shfl_sync(0xffffffffu, hA1, s, 4));
            const __half2 vB0 = u2h(__shfl_sync(0xffffffffu, hB0, s, 4));
            const __half2 vB1 = u2h(__shfl_sync(0xffffffffu, hB1, s, 4));
            aA01[s] = __hfma2(__low2half2(vA0),  wA01[4 * s + 0], aA01[s]);
            aA23[s] = __hfma2(__low2half2(vA0),  wA23[4 * s + 0], aA23[s]);
            aA01[s] = __hfma2(__high2half2(vA0), wA01[4 * s + 1], aA01[s]);
            aA23[s] = __hfma2(__high2half2(vA0), wA23[4 * s + 1], aA23[s]);
            aA01[s] = __hfma2(__low2half2(vA1),  wA01[4 * s + 2], aA01[s]);
            aA23[s] = __hfma2(__low2half2(vA1),  wA23[4 * s + 2], aA23[s]);
            aA01[s] = __hfma2(__high2half2(vA1), wA01[4 * s + 3], aA01[s]);
            aA23[s] = __hfma2(__high2half2(vA1), wA23[4 * s + 3], aA23[s]);
            aB01[s] = __hfma2(__low2half2(vB0),  wB01[4 * s + 0], aB01[s]);
            aB23[s] = __hfma2(__low2half2(vB0),  wB23[4 * s + 0], aB23[s]);
            aB01[s] = __hfma2(__high2half2(vB0), wB01[4 * s + 1], aB01[s]);
            aB23[s] = __hfma2(__high2half2(vB0), wB23[4 * s + 1], aB23[s]);
            aB01[s] = __hfma2(__low2half2(vB1),  wB01[4 * s + 2], aB01[s]);
            aB23[s] = __hfma2(__low2half2(vB1),  wB23[4 * s + 2], aB23[s]);
            aB01[s] = __hfma2(__high2half2(vB1), wB01[4 * s + 3], aB01[s]);
            aB23[s] = __hfma2(__high2half2(vB1), wB23[4 * s + 3], aB23[s]);
        }
        const __half2 sA01 = __hadd2(__hadd2(aA01[0], aA01[1]), __hadd2(aA01[2], aA01[3]));
        const __half2 sA23 = __hadd2(__hadd2(aA23[0], aA23[1]), __hadd2(aA23[2], aA23[3]));
        const __half2 sB01 = __hadd2(__hadd2(aB01[0], aB01[1]), __hadd2(aB01[2], aB01[3]));
        const __half2 sB23 = __hadd2(__hadd2(aB23[0], aB23[1]), __hadd2(aB23[2], aB23[3]));
        // layer 2: f16x2 tanh, fp32 dot with w2, shfl_xor quad reduction
        const float2 tA01 = __half22float2(u2h(tanh2u(h2u(sA01))));
        const float2 tA23 = __half22float2(u2h(tanh2u(h2u(sA23))));
        const float2 tB01 = __half22float2(u2h(tanh2u(h2u(sB01))));
        const float2 tB23 = __half22float2(u2h(tanh2u(h2u(sB23))));
        float pA = fmaf(tA01.x, w2a[0], basea);
        float pB = tA01.y * w2a[1];
        float qA = fmaf(tB01.x, w2b[0], baseb);
        float qB = tB01.y * w2b[1];
        pA = fmaf(tA23.x, w2a[2], pA);
        pB = fmaf(tA23.y, w2a[3], pB);
        qA = fmaf(tB23.x, w2b[2], qA);
        qB = fmaf(tB23.y, w2b[3], qB);
        float p1 = pA + pB, p2 = qA + qB;
        p1 += __shfl_xor_sync(0xffffffffu, p1, 1, 4);
        p2 += __shfl_xor_sync(0xffffffffu, p2, 1, 4);
        p1 += __shfl_xor_sync(0xffffffffu, p1, 2, 4);
        p2 += __shfl_xor_sync(0xffffffffu, p2, 2, 4);
        d0 = fmaf(-0.1f, c0, uc) - p1;
        d1 = fmaf(kr, p1, fmaf(-3.0f, p2, fmaf(-0.1f, c1, kb)));
        d2 = fmaf(-0.1f, c2, kb) + p2;
    };

    float ucur = __ldg(&ue[0]);

    #pragma unroll 1
    for (int t = 0; t < TSEQ; t++) {
        // Emit pre-update state (scan collects x_t before the step).
        if (g == 0)      ybase[t] = make_float2(x0, x1);
        else if (g == 1) xbase[t * 3 + 0] = x0;
        else if (g == 2) xbase[t * 3 + 1] = x1;
        else             xbase[t * 3 + 2] = x2;

        uc = fmaf(ku, ucur, kc);
        if (t + 1 < TSEQ) ucur = __ldg(&ue[t + 1]);   // prefetch next step

        float a0, a1, a2, d0, d1, d2, s0, s1, s2;
        fxu(x0, x1, x2, a0, a1, a2);                               // k1
        s0 = fmaf(0.5f, a0, x0); s1 = fmaf(0.5f, a1, x1); s2 = fmaf(0.5f, a2, x2);
        fxu(s0, s1, s2, d0, d1, d2);                               // k2
        a0 = fmaf(2.0f, d0, a0); a1 = fmaf(2.0f, d1, a1); a2 = fmaf(2.0f, d2, a2);
        s0 = fmaf(0.5f, d0, x0); s1 = fmaf(0.5f, d1, x1); s2 = fmaf(0.5f, d2, x2);
        fxu(s0, s1, s2, d0, d1, d2);                               // k3
        a0 = fmaf(2.0f, d0, a0); a1 = fmaf(2.0f, d1, a1); a2 = fmaf(2.0f, d2, a2);
        s0 = x0 + d0; s1 = x1 + d1; s2 = x2 + d2;
        fxu(s0, s1, s2, d0, d1, d2);                               // k4
        a0 += d0; a1 += d1; a2 += d2;
        const float c6 = 1.0f / 6.0f;
        x0 = fmaf(c6, a0, x0); x1 = fmaf(c6, a1, x1); x2 = fmaf(c6, a2, x2);
    }
}

extern "C" void kernel_launch(void* const* d_in, const int* in_sizes, int n_in,
                              void* d_out, int out_size) {
    (void)in_sizes; (void)n_in; (void)out_size;
    reac_kernel<<<128, 128>>>(
        (const float*)d_in[0],  (const float*)d_in[1],
        (const float*)d_in[2],  (const float*)d_in[3],
        (const float*)d_in[4],  (const float*)d_in[5],
        (const float*)d_in[6],  (const float*)d_in[7],
        (const float*)d_in[8],  (const float*)d_in[9],
        (const float*)d_in[10], (const float*)d_in[11],
        (const float*)d_in[12], (const float*)d_in[13],
        (const float*)d_in[14], (const float*)d_in[15],
        (const float*)d_in[16], (const float*)d_in[17],
        (float*)d_out);
}

// round 11
// speedup vs baseline: 1.5871x; 1.2425x over previous
#include <cuda_runtime.h>
#include <cuda_fp16.h>

#define TSEQ 1024
#define BATCH 4096

__device__ __forceinline__ unsigned tanh2u(unsigned x) {
    unsigned y; asm("tanh.approx.f16x2 %0, %1;" : "=r"(y) : "r"(x)); return y;
}
// pack (lo, hi) floats -> f16x2 (first PTX src lands in the UPPER half)
__device__ __forceinline__ unsigned cvtpack(float lo, float hi) {
    unsigned d; asm("cvt.rn.f16x2.f32 %0, %1, %2;" : "=r"(d) : "f"(hi), "f"(lo));
    return d;
}
// warp-collective 8x8 b16 fragment transpose
__device__ __forceinline__ unsigned movmat_t(unsigned x) {
    unsigned y; asm("movmatrix.sync.aligned.m8n8.trans.b16 %0, %1;" : "=r"(y) : "r"(x));
    return y;
}
// D(16x8,f32) = A(16x16,f16,row) * B(16x8,f16,col) + C
__device__ __forceinline__ void mma16816(
    float& d0, float& d1, float& d2, float& d3,
    unsigned a0, unsigned a1, unsigned a2, unsigned a3,
    unsigned b0, unsigned b1,
    float c0, float c1, float c2, float c3)
{
    asm("mma.sync.aligned.m16n8k16.row.col.f32.f16.f16.f32 "
        "{%0,%1,%2,%3}, {%4,%5,%6,%7}, {%8,%9}, {%10,%11,%12,%13};"
        : "=f"(d0), "=f"(d1), "=f"(d2), "=f"(d3)
        : "r"(a0), "r"(a1), "r"(a2), "r"(a3), "r"(b0), "r"(b1),
          "f"(c0), "f"(c1), "f"(c2), "f"(c3));
}

__device__ __forceinline__ unsigned packw(float x, float y) {
    __half2 h = __floats2half2_rn(x, y);
    return *reinterpret_cast<unsigned*>(&h);
}

__global__ __launch_bounds__(128, 1)
void reac_kernel(
    const float* __restrict__ u,    const float* __restrict__ xz0,
    const float* __restrict__ r1W0, const float* __restrict__ r1b0,
    const float* __restrict__ r1W1, const float* __restrict__ r1b1,
    const float* __restrict__ r1W2, const float* __restrict__ r1b2,
    const float* __restrict__ r2W0, const float* __restrict__ r2b0,
    const float* __restrict__ r2W1, const float* __restrict__ r2b1,
    const float* __restrict__ r2W2, const float* __restrict__ r2b2,
    const float* __restrict__ ymean, const float* __restrict__ ystd,
    const float* __restrict__ umean, const float* __restrict__ ustd,
    float* __restrict__ out)
{
    const int tid  = threadIdx.x;
    const int lane = tid & 31;
    const int q = lane >> 2;     // mma groupID == element within warp
    const int g = lane & 3;      // mma threadID-in-group
    const int e = blockIdx.x * 32 + (tid >> 2);   // global batch element

    // Lane-local hidden units chosen to match the mma B-fragment:
    // lane (q,g) computes h[k] for k in {2g, 2g+1, 2g+8, 2g+9} of element q.
    const int ki[4] = { 2 * g, 2 * g + 1, 2 * g + 8, 2 * g + 9 };
    float w0a[4], b0a[4], w0b0[4], w0b1[4], b0b[4];
    #pragma unroll
    for (int jj = 0; jj < 4; jj++) {
        const int j = ki[jj];
        w0a[jj]  = r1W0[j];        b0a[jj] = r1b0[j];
        w0b0[jj] = r2W0[j];        w0b1[jj] = r2W0[16 + j];
        b0b[jj]  = r2b0[j];
    }

    // Layer-1 A fragments: A[m][k] = W1[k][m] (W1 transposed), row-major.
    // a0:(m, k=2g,2g+1)  a1:(m+8, same k)  a2:(m, k+8)  a3:(m+8, k+8), m=q.
    unsigned A1a[4], A1b[4];
    A1a[0] = packw(r1W1[(2*g)*16 + q],     r1W1[(2*g+1)*16 + q]);
    A1a[1] = packw(r1W1[(2*g)*16 + q + 8], r1W1[(2*g+1)*16 + q + 8]);
    A1a[2] = packw(r1W1[(2*g+8)*16 + q],     r1W1[(2*g+9)*16 + q]);
    A1a[3] = packw(r1W1[(2*g+8)*16 + q + 8], r1W1[(2*g+9)*16 + q + 8]);
    A1b[0] = packw(r2W1[(2*g)*16 + q],     r2W1[(2*g+1)*16 + q]);
    A1b[1] = packw(r2W1[(2*g)*16 + q + 8], r2W1[(2*g+1)*16 + q + 8]);
    A1b[2] = packw(r2W1[(2*g+8)*16 + q],     r2W1[(2*g+9)*16 + q]);
    A1b[3] = packw(r2W1[(2*g+8)*16 + q + 8], r2W1[(2*g+9)*16 + q + 8]);

    // Layer-2 A fragments: w2a lives only in row 0, w2b only in row 1.
    const unsigned A2a0 = (q == 0) ? packw(r1W2[2*g],     r1W2[2*g+1])     : 0u;
    const unsigned A2a2 = (q == 0) ? packw(r1W2[2*g+8],   r1W2[2*g+9])     : 0u;
    const unsigned A2b0 = (q == 1) ? packw(r2W2[2*g],     r2W2[2*g+1])     : 0u;
    const unsigned A2b2 = (q == 1) ? packw(r2W2[2*g+8],   r2W2[2*g+9])     : 0u;

    // Layer-1 biases in C-fragment slots (c0=c1 row m, c2=c3 row m+8).
    const float c1aLo = r1b1[q], c1aHi = r1b1[q + 8];
    const float c1bLo = r2b1[q], c1bHi = r2b1[q + 8];
    // Layer-2 bias: row0 = r1b2, row1 = r2b2.
    const float c2base = (q == 0) ? r1b2[0] : ((q == 1) ? r2b2[0] : 0.0f);

    const float Castd = ystd[0], Cbstd = ystd[1];
    const float Camean = ymean[0], Cbmean = ymean[1];
    const float us = ustd[0], um = umean[0];
    // Normalized-coordinate dynamics:
    //   dCa = uc - 0.1*Ca - f1,  uc = ku*u + kc
    //   dCb = kb - 0.1*Cb + kr*f1 - 3*f2
    //   dCc = kb - 0.1*Cc + f2
    const float ku = 0.1f * us / Castd;
    const float kc = 0.1f * (um - Camean) / Castd;
    const float kb = -0.1f * Cbmean / Cbstd;
    const float kr = Castd / Cbstd;

    float x0 = xz0[e * 3 + 0], x1 = xz0[e * 3 + 1], x2 = xz0[e * 3 + 2];
    const float* ue = u + (size_t)e * TSEQ;
    float2* ybase = (float2*)(out + (size_t)e * TSEQ * 2);
    float* xbase = out + (size_t)BATCH * TSEQ * 2 + (size_t)e * TSEQ * 3;

    const int src1 = q >> 1;        // lane holding p1 for element q
    const int src2 = 4 + (q >> 1);  // lane holding p2 for element q
    const bool hiSel = (q & 1);

    float uc = 0.0f;

    auto fxu = [&](float c0, float c1, float c2, float& d0, float& d1, float& d2) {
        // layer 0: lane-local, emits mma B fragments directly (no shfl)
        const float pa0 = fmaf(c0, w0a[0], b0a[0]);
        const float pa1 = fmaf(c0, w0a[1], b0a[1]);
        const float pa2 = fmaf(c0, w0a[2], b0a[2]);
        const float pa3 = fmaf(c0, w0a[3], b0a[3]);
        const float pb0 = fmaf(c2, w0b1[0], fmaf(c1, w0b0[0], b0b[0]));
        const float pb1 = fmaf(c2, w0b1[1], fmaf(c1, w0b0[1], b0b[1]));
        const float pb2 = fmaf(c2, w0b1[2], fmaf(c1, w0b0[2], b0b[2]));
        const float pb3 = fmaf(c2, w0b1[3], fmaf(c1, w0b0[3], b0b[3]));
        const unsigned hA0 = tanh2u(cvtpack(pa0, pa1));   // k=2g,2g+1
        const unsigned hA1 = tanh2u(cvtpack(pa2, pa3));   // k=2g+8,2g+9
        const unsigned hB0 = tanh2u(cvtpack(pb0, pb1));
        const unsigned hB1 = tanh2u(cvtpack(pb2, pb3));

        // layer 1: one mma per MLP, fp32 accumulate, bias in C
        float dA0, dA1, dA2, dA3, dB0, dB1, dB2, dB3;
        mma16816(dA0, dA1, dA2, dA3, A1a[0], A1a[1], A1a[2], A1a[3],
                 hA0, hA1, c1aLo, c1aLo, c1aHi, c1aHi);
        mma16816(dB0, dB1, dB2, dB3, A1b[0], A1b[1], A1b[2], A1b[3],
                 hB0, hB1, c1bLo, c1bLo, c1bHi, c1bHi);

        // tanh (f16x2) + fragment transpose: D-frag -> B-frag for layer 2
        const unsigned BtA0 = movmat_t(tanh2u(cvtpack(dA0, dA1)));
        const unsigned BtA1 = movmat_t(tanh2u(cvtpack(dA2, dA3)));
        const unsigned BtB0 = movmat_t(tanh2u(cvtpack(dB0, dB1)));
        const unsigned BtB1 = movmat_t(tanh2u(cvtpack(dB2, dB3)));

        // layer 2: chained mmas; p1 accumulates in D row 0, p2 in row 1
        float e0, e1, e2, e3;
        mma16816(e0, e1, e2, e3, A2a0, 0u, A2a2, 0u, BtA0, BtA1,
                 c2base, c2base, 0.0f, 0.0f);
        mma16816(e0, e1, e2, e3, A2b0, 0u, A2b2, 0u, BtB0, BtB1,
                 e0, e1, e2, e3);

        // distribute p1(q), p2(q) to element quads (idx shfl + select)
        const float v0 = __shfl_sync(0xffffffffu, e0, src1, 32);
        const float v1 = __shfl_sync(0xffffffffu, e1, src1, 32);
        const float w0 = __shfl_sync(0xffffffffu, e0, src2, 32);
        const float w1 = __shfl_sync(0xffffffffu, e1, src2, 32);
        const float p1 = hiSel ? v1 : v0;
        const float p2 = hiSel ? w1 : w0;

        d0 = fmaf(-0.1f, c0, uc) - p1;
        d1 = fmaf(kr, p1, fmaf(-3.0f, p2, fmaf(-0.1f, c1, kb)));
        d2 = fmaf(-0.1f, c2, kb) + p2;
    };

    float ucur = __ldg(&ue[0]);

    #pragma unroll 1
    for (int t = 0; t < TSEQ; t++) {
        // Emit pre-update state (scan collects x_t before the step).
        if (g == 0)      ybase[t] = make_float2(x0, x1);
        else if (g == 1) xbase[t * 3 + 0] = x0;
        else if (g == 2) xbase[t * 3 + 1] = x1;
        else             xbase[t * 3 + 2] = x2;

        uc = fmaf(ku, ucur, kc);
        if (t + 1 < TSEQ) ucur = __ldg(&ue[t + 1]);   // prefetch next step

        float a0, a1, a2, d0, d1, d2, s0, s1, s2;
        fxu(x0, x1, x2, a0, a1, a2);                               // k1
        s0 = fmaf(0.5f, a0, x0); s1 = fmaf(0.5f, a1, x1); s2 = fmaf(0.5f, a2, x2);
        fxu(s0, s1, s2, d0, d1, d2);                               // k2
        a0 = fmaf(2.0f, d0, a0); a1 = fmaf(2.0f, d1, a1); a2 = fmaf(2.0f, d2, a2);
        s0 = fmaf(0.5f, d0, x0); s1 = fmaf(0.5f, d1, x1); s2 = fmaf(0.5f, d2, x2);
        fxu(s0, s1, s2, d0, d1, d2);                               // k3
        a0 = fmaf(2.0f, d0, a0); a1 = fmaf(2.0f, d1, a1); a2 = fmaf(2.0f, d2, a2);
        s0 = x0 + d0; s1 = x1 + d1; s2 = x2 + d2;
        fxu(s0, s1, s2, d0, d1, d2);                               // k4
        a0 += d0; a1 += d1; a2 += d2;
        const float c6 = 1.0f / 6.0f;
        x0 = fmaf(c6, a0, x0); x1 = fmaf(c6, a1, x1); x2 = fmaf(c6, a2, x2);
    }
}

extern "C" void kernel_launch(void* const* d_in, const int* in_sizes, int n_in,
                              void* d_out, int out_size) {
    (void)in_sizes; (void)n_in; (void)out_size;
    reac_kernel<<<128, 128>>>(
        (const float*)d_in[0],  (const float*)d_in[1],
        (const float*)d_in[2],  (const float*)d_in[3],
        (const float*)d_in[4],  (const float*)d_in[5],
        (const float*)d_in[6],  (const float*)d_in[7],
        (const float*)d_in[8],  (const float*)d_in[9],
        (const float*)d_in[10], (const float*)d_in[11],
        (const float*)d_in[12], (const float*)d_in[13],
        (const float*)d_in[14], (const float*)d_in[15],
        (const float*)d_in[16], (const float*)d_in[17],
        (float*)d_out);
}

// round 12
// speedup vs baseline: 1.6646x; 1.0488x over previous
#include <cuda_runtime.h>
#include <cuda_fp16.h>

#define TSEQ 1024
#define BATCH 4096

__device__ __forceinline__ unsigned tanh2u(unsigned x) {
    unsigned y; asm("tanh.approx.f16x2 %0, %1;" : "=r"(y) : "r"(x)); return y;
}
// pack (lo, hi) floats -> f16x2 (first PTX src lands in the UPPER half)
__device__ __forceinline__ unsigned cvtpack(float lo, float hi) {
    unsigned d; asm("cvt.rn.f16x2.f32 %0, %1, %2;" : "=r"(d) : "f"(hi), "f"(lo));
    return d;
}
// D(16x8,f32) = A(16x16,f16,row) * B(16x8,f16,col) + C
__device__ __forceinline__ void mma16816(
    float& d0, float& d1, float& d2, float& d3,
    unsigned a0, unsigned a1, unsigned a2, unsigned a3,
    unsigned b0, unsigned b1,
    float c0, float c1, float c2, float c3)
{
    asm("mma.sync.aligned.m16n8k16.row.col.f32.f16.f16.f32 "
        "{%0,%1,%2,%3}, {%4,%5,%6,%7}, {%8,%9}, {%10,%11,%12,%13};"
        : "=f"(d0), "=f"(d1), "=f"(d2), "=f"(d3)
        : "r"(a0), "r"(a1), "r"(a2), "r"(a3), "r"(b0), "r"(b1),
          "f"(c0), "f"(c1), "f"(c2), "f"(c3));
}

__device__ __forceinline__ unsigned packw(float x, float y) {
    __half2 h = __floats2half2_rn(x, y);
    return *reinterpret_cast<unsigned*>(&h);
}

__global__ __launch_bounds__(128, 1)
void reac_kernel(
    const float* __restrict__ u,    const float* __restrict__ xz0,
    const float* __restrict__ r1W0, const float* __restrict__ r1b0,
    const float* __restrict__ r1W1, const float* __restrict__ r1b1,
    const float* __restrict__ r1W2, const float* __restrict__ r1b2,
    const float* __restrict__ r2W0, const float* __restrict__ r2b0,
    const float* __restrict__ r2W1, const float* __restrict__ r2b1,
    const float* __restrict__ r2W2, const float* __restrict__ r2b2,
    const float* __restrict__ ymean, const float* __restrict__ ystd,
    const float* __restrict__ umean, const float* __restrict__ ustd,
    float* __restrict__ out)
{
    const int tid  = threadIdx.x;
    const int lane = tid & 31;
    const int q = lane >> 2;     // mma groupID == element within warp
    const int g = lane & 3;      // mma threadID-in-group
    const int e = blockIdx.x * 32 + (tid >> 2);   // global batch element

    // Layer 0: lane (q,g) computes h[k] of element q for k in
    // {2g, 2g+1, 2g+8, 2g+9} — exactly the mma A-fragment layout for h^T.
    const int ki[4] = { 2 * g, 2 * g + 1, 2 * g + 8, 2 * g + 9 };
    float w0a[4], b0a[4], w0b0[4], w0b1[4], b0b[4];
    #pragma unroll
    for (int jj = 0; jj < 4; jj++) {
        const int j = ki[jj];
        w0a[jj]  = r1W0[j];        b0a[jj] = r1b0[j];
        w0b0[jj] = r2W0[j];        w0b1[jj] = r2W0[16 + j];
        b0b[jj]  = r2b0[j];
    }

    // Layer 1 computed transposed: D^T[elem][unit] = h^T(A) * W1(B) + b1(C).
    // B frag (k16 x n8, col): b0 = W1[2g..2g+1][n], b1 = W1[2g+8..2g+9][n],
    // n = q. lo covers units 0-7 (n=q), hi covers units 8-15 (n=q+8).
    const unsigned BaLo0 = packw(r1W1[(2*g)*16 + q],       r1W1[(2*g+1)*16 + q]);
    const unsigned BaLo1 = packw(r1W1[(2*g+8)*16 + q],     r1W1[(2*g+9)*16 + q]);
    const unsigned BaHi0 = packw(r1W1[(2*g)*16 + 8 + q],   r1W1[(2*g+1)*16 + 8 + q]);
    const unsigned BaHi1 = packw(r1W1[(2*g+8)*16 + 8 + q], r1W1[(2*g+9)*16 + 8 + q]);
    const unsigned BbLo0 = packw(r2W1[(2*g)*16 + q],       r2W1[(2*g+1)*16 + q]);
    const unsigned BbLo1 = packw(r2W1[(2*g+8)*16 + q],     r2W1[(2*g+9)*16 + q]);
    const unsigned BbHi0 = packw(r2W1[(2*g)*16 + 8 + q],   r2W1[(2*g+1)*16 + 8 + q]);
    const unsigned BbHi1 = packw(r2W1[(2*g+8)*16 + 8 + q], r2W1[(2*g+9)*16 + 8 + q]);
    // Layer-1 bias in C: c0,c1 = row q cols 2g,2g+1 -> unit bias (g-dep only).
    const float c1aLo0 = r1b1[2*g],     c1aLo1 = r1b1[2*g + 1];
    const float c1aHi0 = r1b1[2*g + 8], c1aHi1 = r1b1[2*g + 9];
    const float c1bLo0 = r2b1[2*g],     c1bLo1 = r2b1[2*g + 1];
    const float c1bHi0 = r2b1[2*g + 8], c1bHi1 = r2b1[2*g + 9];

    // Layer 2: separate mmas for p1 and p2, weights in row 0 of each A.
    const unsigned A2a0 = (q == 0) ? packw(r1W2[2*g],   r1W2[2*g+1]) : 0u;
    const unsigned A2a2 = (q == 0) ? packw(r1W2[2*g+8], r1W2[2*g+9]) : 0u;
    const unsigned A2b0 = (q == 0) ? packw(r2W2[2*g],   r2W2[2*g+1]) : 0u;
    const unsigned A2b2 = (q == 0) ? packw(r2W2[2*g+8], r2W2[2*g+9]) : 0u;
    const float c2a = (q == 0) ? r1b2[0] : 0.0f;
    const float c2b = (q == 0) ? r2b2[0] : 0.0f;

    const float Castd = ystd[0], Cbstd = ystd[1];
    const float Camean = ymean[0], Cbmean = ymean[1];
    const float us = ustd[0], um = umean[0];
    // Normalized-coordinate dynamics:
    //   dCa = uc - 0.1*Ca - f1,  uc = ku*u + kc
    //   dCb = kb - 0.1*Cb + kr*f1 - 3*f2
    //   dCc = kb - 0.1*Cc + f2
    const float ku = 0.1f * us / Castd;
    const float kc = 0.1f * (um - Camean) / Castd;
    const float kb = -0.1f * Cbmean / Cbstd;
    const float kr = Castd / Cbstd;

    float x0 = xz0[e * 3 + 0], x1 = xz0[e * 3 + 1], x2 = xz0[e * 3 + 2];
    const float* ue = u + (size_t)e * TSEQ;
    float2* ybase = (float2*)(out + (size_t)e * TSEQ * 2);
    float* xbase = out + (size_t)BATCH * TSEQ * 2 + (size_t)e * TSEQ * 3;

    const int src = q >> 1;         // lane (0..3) holding p1/p2 of element q
    const bool hiSel = (q & 1);

    float uc = 0.0f;

    auto fxu = [&](float c0, float c1, float c2, float& d0, float& d1, float& d2) {
        // layer 0: lane-local, emits h^T A-fragments directly (no shfl)
        const float pa0 = fmaf(c0, w0a[0], b0a[0]);
        const float pa1 = fmaf(c0, w0a[1], b0a[1]);
        const float pa2 = fmaf(c0, w0a[2], b0a[2]);
        const float pa3 = fmaf(c0, w0a[3], b0a[3]);
        const float pb0 = fmaf(c2, w0b1[0], fmaf(c1, w0b0[0], b0b[0]));
        const float pb1 = fmaf(c2, w0b1[1], fmaf(c1, w0b0[1], b0b[1]));
        const float pb2 = fmaf(c2, w0b1[2], fmaf(c1, w0b0[2], b0b[2]));
        const float pb3 = fmaf(c2, w0b1[3], fmaf(c1, w0b0[3], b0b[3]));
        const unsigned hA0 = tanh2u(cvtpack(pa0, pa1));   // k=2g,2g+1
        const unsigned hA1 = tanh2u(cvtpack(pa2, pa3));   // k=2g+8,2g+9
        const unsigned hB0 = tanh2u(cvtpack(pb0, pb1));
        const unsigned hB1 = tanh2u(cvtpack(pb2, pb3));

        // layer 1: 4 independent mmas (lo/hi units x 2 MLPs), h as A, W1 as B.
        // Rows 8-15 of A (elements q+8) are zero; d2/d3 unused.
        float zAlo0, zAlo1, zAhi0, zAhi1, zBlo0, zBlo1, zBhi0, zBhi1, junk2, junk3;
        mma16816(zAlo0, zAlo1, junk2, junk3, hA0, 0u, hA1, 0u,
                 BaLo0, BaLo1, c1aLo0, c1aLo1, 0.0f, 0.0f);
        mma16816(zAhi0, zAhi1, junk2, junk3, hA0, 0u, hA1, 0u,
                 BaHi0, BaHi1, c1aHi0, c1aHi1, 0.0f, 0.0f);
        mma16816(zBlo0, zBlo1, junk2, junk3, hB0, 0u, hB1, 0u,
                 BbLo0, BbLo1, c1bLo0, c1bLo1, 0.0f, 0.0f);
        mma16816(zBhi0, zBhi1, junk2, junk3, hB0, 0u, hB1, 0u,
                 BbHi0, BbHi1, c1bHi0, c1bHi1, 0.0f, 0.0f);

        // tanh -> directly layer-2 B-fragments (no movmatrix needed):
        // b0 = t[2g..2g+1][q], b1 = t[2g+8..2g+9][q].
        const unsigned btA0 = tanh2u(cvtpack(zAlo0, zAlo1));
        const unsigned btA1 = tanh2u(cvtpack(zAhi0, zAhi1));
        const unsigned btB0 = tanh2u(cvtpack(zBlo0, zBlo1));
        const unsigned btB1 = tanh2u(cvtpack(zBhi0, zBhi1));

        // layer 2: two independent mmas; p1/p2 land in row 0 (lanes 0-3).
        float eA0, eA1, eB0, eB1;
        mma16816(eA0, eA1, junk2, junk3, A2a0, 0u, A2a2, 0u, btA0, btA1,
                 c2a, c2a, 0.0f, 0.0f);
        mma16816(eB0, eB1, junk2, junk3, A2b0, 0u, A2b2, 0u, btB0, btB1,
                 c2b, c2b, 0.0f, 0.0f);

        // distribute p1(q), p2(q) to element quads (4 parallel idx shfls)
        const float v0 = __shfl_sync(0xffffffffu, eA0, src, 32);
        const float v1 = __shfl_sync(0xffffffffu, eA1, src, 32);
        const float w0 = __shfl_sync(0xffffffffu, eB0, src, 32);
        const float w1 = __shfl_sync(0xffffffffu, eB1, src, 32);
        const float p1 = hiSel ? v1 : v0;
        const float p2 = hiSel ? w1 : w0;

        d0 = fmaf(-0.1f, c0, uc) - p1;
        d1 = fmaf(kr, p1, fmaf(-3.0f, p2, fmaf(-0.1f, c1, kb)));
        d2 = fmaf(-0.1f, c2, kb) + p2;
    };

    float ucur = __ldg(&ue[0]);

    #pragma unroll 1
    for (int t = 0; t < TSEQ; t++) {
        // Emit pre-update state (scan collects x_t before the step).
        if (g == 0)      ybase[t] = make_float2(x0, x1);
        else if (g == 1) xbase[t * 3 + 0] = x0;
        else if (g == 2) xbase[t * 3 + 1] = x1;
        else             xbase[t * 3 + 2] = x2;

        uc = fmaf(ku, ucur, kc);
        if (t + 1 < TSEQ) ucur = __ldg(&ue[t + 1]);   // prefetch next step

        float a0, a1, a2, d0, d1, d2, s0, s1, s2;
        fxu(x0, x1, x2, a0, a1, a2);                               // k1
        s0 = fmaf(0.5f, a0, x0); s1 = fmaf(0.5f, a1, x1); s2 = fmaf(0.5f, a2, x2);
        fxu(s0, s1, s2, d0, d1, d2);                               // k2
        a0 = fmaf(2.0f, d0, a0); a1 = fmaf(2.0f, d1, a1); a2 = fmaf(2.0f, d2, a2);
        s0 = fmaf(0.5f, d0, x0); s1 = fmaf(0.5f, d1, x1); s2 = fmaf(0.5f, d2, x2);
        fxu(s0, s1, s2, d0, d1, d2);                               // k3
        a0 = fmaf(2.0f, d0, a0); a1 = fmaf(2.0f, d1, a1); a2 = fmaf(2.0f, d2, a2);
        s0 = x0 + d0; s1 = x1 + d1; s2 = x2 + d2;
        fxu(s0, s1, s2, d0, d1, d2);                               // k4
        a0 += d0; a1 += d1; a2 += d2;
        const float c6 = 1.0f / 6.0f;
        x0 = fmaf(c6, a0, x0); x1 = fmaf(c6, a1, x1); x2 = fmaf(c6, a2, x2);
    }
}

extern "C" void kernel_launch(void* const* d_in, const int* in_sizes, int n_in,
                              void* d_out, int out_size) {
    (void)in_sizes; (void)n_in; (void)out_size;
    reac_kernel<<<128, 128>>>(
        (const float*)d_in[0],  (const float*)d_in[1],
        (const float*)d_in[2],  (const float*)d_in[3],
        (const float*)d_in[4],  (const float*)d_in[5],
        (const float*)d_in[6],  (const float*)d_in[7],
        (const float*)d_in[8],  (const float*)d_in[9],
        (const float*)d_in[10], (const float*)d_in[11],
        (const float*)d_in[12], (const float*)d_in[13],
        (const float*)d_in[14], (const float*)d_in[15],
        (const float*)d_in[16], (const float*)d_in[17],
        (float*)d_out);
}

// round 13
// speedup vs baseline: 1.7179x; 1.0320x over previous
#include <cuda_runtime.h>
#include <cuda_fp16.h>

#define TSEQ 1024
#define BATCH 4096

__device__ __forceinline__ unsigned tanh2u(unsigned x) {
    unsigned y; asm("tanh.approx.f16x2 %0, %1;" : "=r"(y) : "r"(x)); return y;
}
// pack (lo, hi) floats -> f16x2 (first PTX src lands in the UPPER half)
__device__ __forceinline__ unsigned cvtpack(float lo, float hi) {
    unsigned d; asm("cvt.rn.f16x2.f32 %0, %1, %2;" : "=r"(d) : "f"(hi), "f"(lo));
    return d;
}
__device__ __forceinline__ __half2 u2h(unsigned u) { return *reinterpret_cast<__half2*>(&u); }
__device__ __forceinline__ unsigned h2u(__half2 h) { return *reinterpret_cast<unsigned*>(&h); }

// D(16x8,f32) = A(16x16,f16,row) * B(16x8,f16,col) + C   (f32 accumulators)
__device__ __forceinline__ void mma16816(
    float& d0, float& d1, float& d2, float& d3,
    unsigned a0, unsigned a1, unsigned a2, unsigned a3,
    unsigned b0, unsigned b1,
    float c0, float c1, float c2, float c3)
{
    asm("mma.sync.aligned.m16n8k16.row.col.f32.f16.f16.f32 "
        "{%0,%1,%2,%3}, {%4,%5,%6,%7}, {%8,%9}, {%10,%11,%12,%13};"
        : "=f"(d0), "=f"(d1), "=f"(d2), "=f"(d3)
        : "r"(a0), "r"(a1), "r"(a2), "r"(a3), "r"(b0), "r"(b1),
          "f"(c0), "f"(c1), "f"(c2), "f"(c3));
}
// f16-D variant: D, C are f16x2 pairs -> output feeds tanh2u directly
__device__ __forceinline__ void mma16816h(
    unsigned& d0, unsigned& d1,
    unsigned a0, unsigned a1, unsigned a2, unsigned a3,
    unsigned b0, unsigned b1,
    unsigned c0, unsigned c1)
{
    asm("mma.sync.aligned.m16n8k16.row.col.f16.f16.f16.f16 "
        "{%0,%1}, {%2,%3,%4,%5}, {%6,%7}, {%8,%9};"
        : "=r"(d0), "=r"(d1)
        : "r"(a0), "r"(a1), "r"(a2), "r"(a3), "r"(b0), "r"(b1),
          "r"(c0), "r"(c1));
}

__device__ __forceinline__ unsigned packw(float x, float y) {
    __half2 h = __floats2half2_rn(x, y);
    return *reinterpret_cast<unsigned*>(&h);
}

__global__ __launch_bounds__(128, 1)
void reac_kernel(
    const float* __restrict__ u,    const float* __restrict__ xz0,
    const float* __restrict__ r1W0, const float* __restrict__ r1b0,
    const float* __restrict__ r1W1, const float* __restrict__ r1b1,
    const float* __restrict__ r1W2, const float* __restrict__ r1b2,
    const float* __restrict__ r2W0, const float* __restrict__ r2b0,
    const float* __restrict__ r2W1, const float* __restrict__ r2b1,
    const float* __restrict__ r2W2, const float* __restrict__ r2b2,
    const float* __restrict__ ymean, const float* __restrict__ ystd,
    const float* __restrict__ umean, const float* __restrict__ ustd,
    float* __restrict__ out)
{
    const int tid  = threadIdx.x;
    const int lane = tid & 31;
    const int q = lane >> 2;     // mma groupID == element within warp
    const int g = lane & 3;      // mma threadID-in-group
    const int e = blockIdx.x * 32 + (tid >> 2);   // global batch element

    // Layer 0: lane (q,g) owns h[k] of element q, k in {2g,2g+1,2g+8,2g+9}
    // = exactly the h^T A-fragment layout.
    const int ki[4] = { 2 * g, 2 * g + 1, 2 * g + 8, 2 * g + 9 };
    float w0a[4], b0a[4], w0b0[4], w0b1[4], b0b[4];
    #pragma unroll
    for (int jj = 0; jj < 4; jj++) {
        const int j = ki[jj];
        w0a[jj]  = r1W0[j];        b0a[jj] = r1b0[j];
        w0b0[jj] = r2W0[j];        w0b1[jj] = r2W0[16 + j];
        b0b[jj]  = r2b0[j];
    }

    // Layer-1 B fragments (W1, f16), D^T[elem][unit] orientation (as R12).
    const unsigned BaLo0 = packw(r1W1[(2*g)*16 + q],       r1W1[(2*g+1)*16 + q]);
    const unsigned BaLo1 = packw(r1W1[(2*g+8)*16 + q],     r1W1[(2*g+9)*16 + q]);
    const unsigned BaHi0 = packw(r1W1[(2*g)*16 + 8 + q],   r1W1[(2*g+1)*16 + 8 + q]);
    const unsigned BaHi1 = packw(r1W1[(2*g+8)*16 + 8 + q], r1W1[(2*g+9)*16 + 8 + q]);
    const unsigned BbLo0 = packw(r2W1[(2*g)*16 + q],       r2W1[(2*g+1)*16 + q]);
    const unsigned BbLo1 = packw(r2W1[(2*g+8)*16 + q],     r2W1[(2*g+9)*16 + q]);
    const unsigned BbHi0 = packw(r2W1[(2*g)*16 + 8 + q],   r2W1[(2*g+1)*16 + 8 + q]);
    const unsigned BbHi1 = packw(r2W1[(2*g+8)*16 + 8 + q], r2W1[(2*g+9)*16 + 8 + q]);
    // Layer-1 biases as f16x2 C fragments (unit-indexed, g-dependent).
    const unsigned c1aLoP = packw(r1b1[2*g],     r1b1[2*g+1]);
    const unsigned c1aHiP = packw(r1b1[2*g+8],   r1b1[2*g+9]);
    const unsigned c1bLoP = packw(r2b1[2*g],     r2b1[2*g+1]);
    const unsigned c1bHiP = packw(r2b1[2*g+8],   r2b1[2*g+9]);

    // Layer 2: w2 rows live on q==0 lanes; p1/p2 land in D row 0.
    const unsigned A2a0 = (q == 0) ? packw(r1W2[2*g],   r1W2[2*g+1]) : 0u;
    const unsigned A2a2 = (q == 0) ? packw(r1W2[2*g+8], r1W2[2*g+9]) : 0u;
    const unsigned A2b0 = (q == 0) ? packw(r2W2[2*g],   r2W2[2*g+1]) : 0u;
    const unsigned A2b2 = (q == 0) ? packw(r2W2[2*g+8], r2W2[2*g+9]) : 0u;
    const float c2a = (q == 0) ? r1b2[0] : 0.0f;
    const float c2b = (q == 0) ? r2b2[0] : 0.0f;

    const float Castd = ystd[0], Cbstd = ystd[1];
    const float Camean = ymean[0], Cbmean = ymean[1];
    const float us = ustd[0], um = umean[0];
    // Normalized dynamics: d0 = uc-0.1c0-p1; d1 = kb-0.1c1+kr*p1-3p2;
    //                      d2 = kb-0.1c2+p2;  uc = ku*u+kc
    const float ku = 0.1f * us / Castd;
    const float kc = 0.1f * (um - Camean) / Castd;
    const float kb = -0.1f * Cbmean / Cbstd;
    const float kr = Castd / Cbstd;

    // Fast-path p-coefficient f16x2 constants per transition coef gamma:
    // preactA' = baseA - g*w0a*p1 ; preactB' = baseB + g*kr*w0b0*p1
    //                                         + g*(w0b1-3*w0b0)*p2
    const float gv[3] = { 0.5f, 1.0f, 1.0f / 6.0f };
    unsigned wpA01[3], wpA23[3], wpB1_01[3], wpB1_23[3], wpB2_01[3], wpB2_23[3];
    #pragma unroll
    for (int i = 0; i < 3; i++) {
        const float gmm = gv[i];
        wpA01[i]  = packw(-gmm * w0a[0], -gmm * w0a[1]);
        wpA23[i]  = packw(-gmm * w0a[2], -gmm * w0a[3]);
        wpB1_01[i] = packw(gmm * kr * w0b0[0], gmm * kr * w0b0[1]);
        wpB1_23[i] = packw(gmm * kr * w0b0[2], gmm * kr * w0b0[3]);
        wpB2_01[i] = packw(gmm * (w0b1[0] - 3.0f * w0b0[0]),
                           gmm * (w0b1[1] - 3.0f * w0b0[1]));
        wpB2_23[i] = packw(gmm * (w0b1[2] - 3.0f * w0b0[2]),
                           gmm * (w0b1[3] - 3.0f * w0b0[3]));
    }

    float x0 = xz0[e * 3 + 0], x1 = xz0[e * 3 + 1], x2 = xz0[e * 3 + 2];
    const float* ue = u + (size_t)e * TSEQ;
    float2* ybase = (float2*)(out + (size_t)e * TSEQ * 2);
    float* xbase = out + (size_t)BATCH * TSEQ * 2 + (size_t)e * TSEQ * 3;

    const int src = q >> 1;
    const bool hiSel = (q & 1);

    // The on-chain stage: tanh -> 4x f16 mma -> tanh -> 2x f32 mma ->
    // cvtpack p -> 2 shfls -> half select. Returns p as replicated half2.
    auto runStage = [&](unsigned pA01, unsigned pA23, unsigned pB01, unsigned pB23,
                        __half2& p1h, __half2& p2h) {
        const unsigned hA0 = tanh2u(pA01);
        const unsigned hA1 = tanh2u(pA23);
        const unsigned hB0 = tanh2u(pB01);
        const unsigned hB1 = tanh2u(pB23);
        unsigned zA0, zA1, zB0, zB1, jk;
        mma16816h(zA0, jk, hA0, 0u, hA1, 0u, BaLo0, BaLo1, c1aLoP, 0u);
        mma16816h(zA1, jk, hA0, 0u, hA1, 0u, BaHi0, BaHi1, c1aHiP, 0u);
        mma16816h(zB0, jk, hB0, 0u, hB1, 0u, BbLo0, BbLo1, c1bLoP, 0u);
        mma16816h(zB1, jk, hB0, 0u, hB1, 0u, BbHi0, BbHi1, c1bHiP, 0u);
        const unsigned tA0 = tanh2u(zA0), tA1 = tanh2u(zA1);
        const unsigned tB0 = tanh2u(zB0), tB1 = tanh2u(zB1);
        float eA0, eA1, eB0, eB1, j2, j3;
        mma16816(eA0, eA1, j2, j3, A2a0, 0u, A2a2, 0u, tA0, tA1,
                 c2a, c2a, 0.0f, 0.0f);
        mma16816(eB0, eB1, j2, j3, A2b0, 0u, A2b2, 0u, tB0, tB1,
                 c2b, c2b, 0.0f, 0.0f);
        const unsigned pu1 = cvtpack(eA0, eA1);
        const unsigned pu2 = cvtpack(eB0, eB1);
        const unsigned v1 = __shfl_sync(0xffffffffu, pu1, src, 32);
        const unsigned v2 = __shfl_sync(0xffffffffu, pu2, src, 32);
        p1h = hiSel ? __high2half2(u2h(v1)) : __low2half2(u2h(v1));
        p2h = hiSel ? __high2half2(u2h(v2)) : __low2half2(u2h(v2));
    };

    // Off-path base builders (fp32 -> f16x2).
    auto mkBaseA = [&](float s0b, unsigned& b01, unsigned& b23) {
        b01 = cvtpack(fmaf(w0a[0], s0b, b0a[0]), fmaf(w0a[1], s0b, b0a[1]));
        b23 = cvtpack(fmaf(w0a[2], s0b, b0a[2]), fmaf(w0a[3], s0b, b0a[3]));
    };
    auto mkBaseB = [&](float s1b, float s2b, unsigned& b01, unsigned& b23) {
        b01 = cvtpack(fmaf(w0b1[0], s2b, fmaf(w0b0[0], s1b, b0b[0])),
                      fmaf(w0b1[1], s2b, fmaf(w0b0[1], s1b, b0b[1])));
        b23 = cvtpack(fmaf(w0b1[2], s2b, fmaf(w0b0[2], s1b, b0b[2])),
                      fmaf(w0b1[3], s2b, fmaf(w0b0[3], s1b, b0b[3])));
    };
    // On-chain fast path: 1 HFMA2 (A) / 2 HFMA2 (B) from p to next preacts.
    auto fastPath = [&](int gi, __half2 p1h, __half2 p2h,
                        unsigned bA01, unsigned bA23, unsigned bB01, unsigned bB23,
                        unsigned& pA01, unsigned& pA23, unsigned& pB01, unsigned& pB23) {
        pA01 = h2u(__hfma2(u2h(wpA01[gi]), p1h, u2h(bA01)));
        pA23 = h2u(__hfma2(u2h(wpA23[gi]), p1h, u2h(bA23)));
        pB01 = h2u(__hfma2(u2h(wpB2_01[gi]), p2h,
                   __hfma2(u2h(wpB1_01[gi]), p1h, u2h(bB01))));
        pB23 = h2u(__hfma2(u2h(wpB2_23[gi]), p2h,
                   __hfma2(u2h(wpB1_23[gi]), p1h, u2h(bB23))));
    };

    // Initial k1 preacts from x.
    unsigned pA01, pA23, pB01, pB23;
    pA01 = cvtpack(fmaf(w0a[0], x0, b0a[0]), fmaf(w0a[1], x0, b0a[1]));
    pA23 = cvtpack(fmaf(w0a[2], x0, b0a[2]), fmaf(w0a[3], x0, b0a[3]));
    pB01 = cvtpack(fmaf(w0b1[0], x2, fmaf(w0b0[0], x1, b0b[0])),
                   fmaf(w0b1[1], x2, fmaf(w0b0[1], x1, b0b[1])));
    pB23 = cvtpack(fmaf(w0b1[2], x2, fmaf(w0b0[2], x1, b0b[2])),
                   fmaf(w0b1[3], x2, fmaf(w0b0[3], x1, b0b[3])));

    float ucur = __ldg(&ue[0]);

    #pragma unroll 1
    for (int t = 0; t < TSEQ; t++) {
        // Emit pre-update state.
        if (g == 0)      ybase[t] = make_float2(x0, x1);
        else if (g == 1) xbase[t * 3 + 0] = x0;
        else if (g == 2) xbase[t * 3 + 1] = x1;
        else             xbase[t * 3 + 2] = x2;

        const float uc = fmaf(ku, ucur, kc);
        if (t + 1 < TSEQ) ucur = __ldg(&ue[t + 1]);

        __half2 p1h, p2h;
        float p1f, p2f, d0, d1, d2;
        unsigned bA01, bA23, bB01, bB23;

        // T1 base (c = x, gamma = 1/2), ready before stage-1 p arrives.
        mkBaseA(fmaf(0.5f, fmaf(-0.1f, x0, uc), x0), bA01, bA23);
        mkBaseB(fmaf(0.5f, fmaf(-0.1f, x1, kb), x1),
                fmaf(0.5f, fmaf(-0.1f, x2, kb), x2), bB01, bB23);

        // ---- stage 1 (k1) ----
        runStage(pA01, pA23, pB01, pB23, p1h, p2h);
        fastPath(0, p1h, p2h, bA01, bA23, bB01, bB23, pA01, pA23, pB01, pB23);
        p1f = __half2float(__low2half(p1h)); p2f = __half2float(__low2half(p2h));
        d0 = fmaf(-0.1f, x0, uc) - p1f;
        d1 = fmaf(kr, p1f, fmaf(-3.0f, p2f, fmaf(-0.1f, x1, kb)));
        d2 = fmaf(-0.1f, x2, kb) + p2f;
        float a0 = d0, a1 = d1, a2 = d2;
        float c20 = fmaf(0.5f, d0, x0), c21 = fmaf(0.5f, d1, x1), c22 = fmaf(0.5f, d2, x2);
        // T2 base (c = c2, gamma = 1/2)
        mkBaseA(fmaf(0.5f, fmaf(-0.1f, c20, uc), x0), bA01, bA23);
        mkBaseB(fmaf(0.5f, fmaf(-0.1f, c21, kb), x1),
                fmaf(0.5f, fmaf(-0.1f, c22, kb), x2), bB01, bB23);

        // ---- stage 2 (k2) ----
        runStage(pA01, pA23, pB01, pB23, p1h, p2h);
        fastPath(0, p1h, p2h, bA01, bA23, bB01, bB23, pA01, pA23, pB01, pB23);
        p1f = __half2float(__low2half(p1h)); p2f = __half2float(__low2half(p2h));
        d0 = fmaf(-0.1f, c20, uc) - p1f;
        d1 = fmaf(kr, p1f, fmaf(-3.0f, p2f, fmaf(-0.1f, c21, kb)));
        d2 = fmaf(-0.1f, c22, kb) + p2f;
        a0 = fmaf(2.0f, d0, a0); a1 = fmaf(2.0f, d1, a1); a2 = fmaf(2.0f, d2, a2);
        float c30 = fmaf(0.5f, d0, x0), c31 = fmaf(0.5f, d1, x1), c32 = fmaf(0.5f, d2, x2);
        // T3 base (c = c3, gamma = 1)
        mkBaseA(x0 + fmaf(-0.1f, c30, uc), bA01, bA23);
        mkBaseB(x1 + fmaf(-0.1f, c31, kb), x2 + fmaf(-0.1f, c32, kb), bB01, bB23);

        // ---- stage 3 (k3) ----
        runStage(pA01, pA23, pB01, pB23, p1h, p2h);
        fastPath(1, p1h, p2h, bA01, bA23, bB01, bB23, pA01, pA23, pB01, pB23);
        p1f = __half2float(__low2half(p1h)); p2f = __half2float(__low2half(p2h));
        d0 = fmaf(-0.1f, c30, uc) - p1f;
        d1 = fmaf(kr, p1f, fmaf(-3.0f, p2f, fmaf(-0.1f, c31, kb)));
        d2 = fmaf(-0.1f, c32, kb) + p2f;
        a0 = fmaf(2.0f, d0, a0); a1 = fmaf(2.0f, d1, a1); a2 = fmaf(2.0f, d2, a2);
        float c40 = x0 + d0, c41 = x1 + d1, c42 = x2 + d2;
        // T4 base (x_new path, gamma = 1/6): s = x + (a + d4_nop)/6
        const float c6 = 1.0f / 6.0f;
        mkBaseA(fmaf(c6, a0 + fmaf(-0.1f, c40, uc), x0), bA01, bA23);
        mkBaseB(fmaf(c6, a1 + fmaf(-0.1f, c41, kb), x1),
                fmaf(c6, a2 + fmaf(-0.1f, c42, kb), x2), bB01, bB23);

        // ---- stage 4 (k4) ----
        runStage(pA01, pA23, pB01, pB23, p1h, p2h);
        fastPath(2, p1h, p2h, bA01, bA23, bB01, bB23, pA01, pA23, pB01, pB23);
        p1f = __half2float(__low2half(p1h)); p2f = __half2float(__low2half(p2h));
        d0 = fmaf(-0.1f, c40, uc) - p1f;
        d1 = fmaf(kr, p1f, fmaf(-3.0f, p2f, fmaf(-0.1f, c41, kb)));
        d2 = fmaf(-0.1f, c42, kb) + p2f;
        x0 = fmaf(c6, a0 + d0, x0);
        x1 = fmaf(c6, a1 + d1, x1);
        x2 = fmaf(c6, a2 + d2, x2);
    }
}

extern "C" void kernel_launch(void* const* d_in, const int* in_sizes, int n_in,
                              void* d_out, int out_size) {
    (void)in_sizes; (void)n_in; (void)out_size;
    reac_kernel<<<128, 128>>>(
        (const float*)d_in[0],  (const float*)d_in[1],
        (const float*)d_in[2],  (const float*)d_in[3],
        (const float*)d_in[4],  (const float*)d_in[5],
        (const float*)d_in[6],  (const float*)d_in[7],
        (const float*)d_in[8],  (const float*)d_in[9],
        (const float*)d_in[10], (const float*)d_in[11],
        (const float*)d_in[12], (const float*)d_in[13],
        (const float*)d_in[14], (const float*)d_in[15],
        (const float*)d_in[16], (const float*)d_in[17],
        (float*)d_out);
}

// round 14
// speedup vs baseline: 2.0108x; 1.1705x over previous
#include <cuda_runtime.h>
#include <cuda_fp16.h>

#define TSEQ 1024
#define BATCH 4096

__device__ __forceinline__ unsigned tanh2u(unsigned x) {
    unsigned y; asm("tanh.approx.f16x2 %0, %1;" : "=r"(y) : "r"(x)); return y;
}
// pack (lo, hi) floats -> f16x2 (first PTX src lands in the UPPER half)
__device__ __forceinline__ unsigned cvtpack(float lo, float hi) {
    unsigned d; asm("cvt.rn.f16x2.f32 %0, %1, %2;" : "=r"(d) : "f"(hi), "f"(lo));
    return d;
}
__device__ __forceinline__ __half2 u2h(unsigned u) { return *reinterpret_cast<__half2*>(&u); }
__device__ __forceinline__ unsigned h2u(__half2 h) { return *reinterpret_cast<unsigned*>(&h); }

// f16-D m16n8k16 mma: D,C are f16x2 pairs
__device__ __forceinline__ void mma16816h(
    unsigned& d0, unsigned& d1,
    unsigned a0, unsigned a1, unsigned a2, unsigned a3,
    unsigned b0, unsigned b1,
    unsigned c0, unsigned c1)
{
    asm("mma.sync.aligned.m16n8k16.row.col.f16.f16.f16.f16 "
        "{%0,%1}, {%2,%3,%4,%5}, {%6,%7}, {%8,%9};"
        : "=r"(d0), "=r"(d1)
        : "r"(a0), "r"(a1), "r"(a2), "r"(a3), "r"(b0), "r"(b1),
          "r"(c0), "r"(c1));
}

__device__ __forceinline__ unsigned packw(float x, float y) {
    __half2 h = __floats2half2_rn(x, y);
    return *reinterpret_cast<unsigned*>(&h);
}

__global__ __launch_bounds__(128, 1)
void reac_kernel(
    const float* __restrict__ u,    const float* __restrict__ xz0,
    const float* __restrict__ r1W0, const float* __restrict__ r1b0,
    const float* __restrict__ r1W1, const float* __restrict__ r1b1,
    const float* __restrict__ r1W2, const float* __restrict__ r1b2,
    const float* __restrict__ r2W0, const float* __restrict__ r2b0,
    const float* __restrict__ r2W1, const float* __restrict__ r2b1,
    const float* __restrict__ r2W2, const float* __restrict__ r2b2,
    const float* __restrict__ ymean, const float* __restrict__ ystd,
    const float* __restrict__ umean, const float* __restrict__ ustd,
    float* __restrict__ out)
{
    const int tid  = threadIdx.x;
    const int lane = tid & 31;
    const int q = lane >> 2;     // mma groupID == element within warp
    const int g = lane & 3;      // mma threadID-in-group
    const int e = blockIdx.x * 32 + (tid >> 2);   // global batch element

    // Layer 0: lane (q,g) owns h[k] of element q, k in {2g,2g+1,2g+8,2g+9}
    // = exactly the h^T A-fragment layout.
    const int ki[4] = { 2 * g, 2 * g + 1, 2 * g + 8, 2 * g + 9 };
    float w0a[4], b0a[4], w0b0[4], w0b1[4], b0b[4];
    #pragma unroll
    for (int jj = 0; jj < 4; jj++) {
        const int j = ki[jj];
        w0a[jj]  = r1W0[j];        b0a[jj] = r1b0[j];
        w0b0[jj] = r2W0[j];        w0b1[jj] = r2W0[16 + j];
        b0b[jj]  = r2b0[j];
    }

    // Layer-1 B fragments (W1, f16), D^T[elem][unit] orientation.
    const unsigned BaLo0 = packw(r1W1[(2*g)*16 + q],       r1W1[(2*g+1)*16 + q]);
    const unsigned BaLo1 = packw(r1W1[(2*g+8)*16 + q],     r1W1[(2*g+9)*16 + q]);
    const unsigned BaHi0 = packw(r1W1[(2*g)*16 + 8 + q],   r1W1[(2*g+1)*16 + 8 + q]);
    const unsigned BaHi1 = packw(r1W1[(2*g+8)*16 + 8 + q], r1W1[(2*g+9)*16 + 8 + q]);
    const unsigned BbLo0 = packw(r2W1[(2*g)*16 + q],       r2W1[(2*g+1)*16 + q]);
    const unsigned BbLo1 = packw(r2W1[(2*g+8)*16 + q],     r2W1[(2*g+9)*16 + q]);
    const unsigned BbHi0 = packw(r2W1[(2*g)*16 + 8 + q],   r2W1[(2*g+1)*16 + 8 + q]);
    const unsigned BbHi1 = packw(r2W1[(2*g+8)*16 + 8 + q], r2W1[(2*g+9)*16 + 8 + q]);
    // Layer-1 biases as f16x2 C fragments (unit-indexed, g-dependent).
    const unsigned c1aLoP = packw(r1b1[2*g],     r1b1[2*g+1]);
    const unsigned c1aHiP = packw(r1b1[2*g+8],   r1b1[2*g+9]);
    const unsigned c1bLoP = packw(r2b1[2*g],     r2b1[2*g+1]);
    const unsigned c1bHiP = packw(r2b1[2*g+8],   r2b1[2*g+9]);

    // Layer 2 re-oriented: A = t^T (the layer-1 tanh output fragment),
    // B = w2 replicated across all 8 columns -> D[elem][n] = p(elem) for
    // every n. Lane (q,g) gets d0 = (p(q), p(q)) — replicated f16x2,
    // no shfl, no cvt. C adds b2 to every column.
    const unsigned W2a0 = packw(r1W2[2*g],   r1W2[2*g+1]);
    const unsigned W2a1 = packw(r1W2[2*g+8], r1W2[2*g+9]);
    const unsigned W2b0 = packw(r2W2[2*g],   r2W2[2*g+1]);
    const unsigned W2b1 = packw(r2W2[2*g+8], r2W2[2*g+9]);
    const unsigned c2aP = packw(r1b2[0], r1b2[0]);
    const unsigned c2bP = packw(r2b2[0], r2b2[0]);

    const float Castd = ystd[0], Cbstd = ystd[1];
    const float Camean = ymean[0], Cbmean = ymean[1];
    const float us = ustd[0], um = umean[0];
    // Normalized dynamics: d0 = uc-0.1c0-p1; d1 = kb-0.1c1+kr*p1-3p2;
    //                      d2 = kb-0.1c2+p2;  uc = ku*u+kc
    const float ku = 0.1f * us / Castd;
    const float kc = 0.1f * (um - Camean) / Castd;
    const float kb = -0.1f * Cbmean / Cbstd;
    const float kr = Castd / Cbstd;

    // Fast-path p-coefficient f16x2 constants per transition coef gamma:
    // preactA' = baseA - g*w0a*p1 ; preactB' = baseB + g*kr*w0b0*p1
    //                                         + g*(w0b1-3*w0b0)*p2
    const float gv[3] = { 0.5f, 1.0f, 1.0f / 6.0f };
    unsigned wpA01[3], wpA23[3], wpB1_01[3], wpB1_23[3], wpB2_01[3], wpB2_23[3];
    #pragma unroll
    for (int i = 0; i < 3; i++) {
        const float gmm = gv[i];
        wpA01[i]  = packw(-gmm * w0a[0], -gmm * w0a[1]);
        wpA23[i]  = packw(-gmm * w0a[2], -gmm * w0a[3]);
        wpB1_01[i] = packw(gmm * kr * w0b0[0], gmm * kr * w0b0[1]);
        wpB1_23[i] = packw(gmm * kr * w0b0[2], gmm * kr * w0b0[3]);
        wpB2_01[i] = packw(gmm * (w0b1[0] - 3.0f * w0b0[0]),
                           gmm * (w0b1[1] - 3.0f * w0b0[1]));
        wpB2_23[i] = packw(gmm * (w0b1[2] - 3.0f * w0b0[2]),
                           gmm * (w0b1[3] - 3.0f * w0b0[3]));
    }

    float x0 = xz0[e * 3 + 0], x1 = xz0[e * 3 + 1], x2 = xz0[e * 3 + 2];
    const float* ue = u + (size_t)e * TSEQ;
    float2* ybase = (float2*)(out + (size_t)e * TSEQ * 2);
    float* xbase = out + (size_t)BATCH * TSEQ * 2 + (size_t)e * TSEQ * 3;

    // On-chain stage: tanh -> 4x mma1h -> tanh -> 2x mma2h. p arrives at
    // every lane as replicated f16x2 straight out of the mma D fragment.
    auto runStage = [&](unsigned pA01, unsigned pA23, unsigned pB01, unsigned pB23,
                        __half2& p1h, __half2& p2h) {
        const unsigned hA0 = tanh2u(pA01);
        const unsigned hA1 = tanh2u(pA23);
        const unsigned hB0 = tanh2u(pB01);
        const unsigned hB1 = tanh2u(pB23);
        unsigned zA0, zA1, zB0, zB1, jk;
        mma16816h(zA0, jk, hA0, 0u, hA1, 0u, BaLo0, BaLo1, c1aLoP, 0u);
        mma16816h(zA1, jk, hA0, 0u, hA1, 0u, BaHi0, BaHi1, c1aHiP, 0u);
        mma16816h(zB0, jk, hB0, 0u, hB1, 0u, BbLo0, BbLo1, c1bLoP, 0u);
        mma16816h(zB1, jk, hB0, 0u, hB1, 0u, BbHi0, BbHi1, c1bHiP, 0u);
        const unsigned tA0 = tanh2u(zA0), tA1 = tanh2u(zA1);
        const unsigned tB0 = tanh2u(zB0), tB1 = tanh2u(zB1);
        unsigned pd1, pd2;
        mma16816h(pd1, jk, tA0, 0u, tA1, 0u, W2a0, W2a1, c2aP, 0u);
        mma16816h(pd2, jk, tB0, 0u, tB1, 0u, W2b0, W2b1, c2bP, 0u);
        p1h = u2h(pd1);
        p2h = u2h(pd2);
    };

    // Off-path base builders (fp32 -> f16x2).
    auto mkBaseA = [&](float s0b, unsigned& b01, unsigned& b23) {
        b01 = cvtpack(fmaf(w0a[0], s0b, b0a[0]), fmaf(w0a[1], s0b, b0a[1]));
        b23 = cvtpack(fmaf(w0a[2], s0b, b0a[2]), fmaf(w0a[3], s0b, b0a[3]));
    };
    auto mkBaseB = [&](float s1b, float s2b, unsigned& b01, unsigned& b23) {
        b01 = cvtpack(fmaf(w0b1[0], s2b, fmaf(w0b0[0], s1b, b0b[0])),
                      fmaf(w0b1[1], s2b, fmaf(w0b0[1], s1b, b0b[1])));
        b23 = cvtpack(fmaf(w0b1[2], s2b, fmaf(w0b0[2], s1b, b0b[2])),
                      fmaf(w0b1[3], s2b, fmaf(w0b0[3], s1b, b0b[3])));
    };
    // On-chain fast path: 1 HFMA2 (A) / 2 HFMA2 (B) from p to next preacts.
    auto fastPath = [&](int gi, __half2 p1h, __half2 p2h,
                        unsigned bA01, unsigned bA23, unsigned bB01, unsigned bB23,
                        unsigned& pA01, unsigned& pA23, unsigned& pB01, unsigned& pB23) {
        pA01 = h2u(__hfma2(u2h(wpA01[gi]), p1h, u2h(bA01)));
        pA23 = h2u(__hfma2(u2h(wpA23[gi]), p1h, u2h(bA23)));
        pB01 = h2u(__hfma2(u2h(wpB2_01[gi]), p2h,
                   __hfma2(u2h(wpB1_01[gi]), p1h, u2h(bB01))));
        pB23 = h2u(__hfma2(u2h(wpB2_23[gi]), p2h,
                   __hfma2(u2h(wpB1_23[gi]), p1h, u2h(bB23))));
    };

    // Initial k1 preacts from x.
    unsigned pA01, pA23, pB01, pB23;
    pA01 = cvtpack(fmaf(w0a[0], x0, b0a[0]), fmaf(w0a[1], x0, b0a[1]));
    pA23 = cvtpack(fmaf(w0a[2], x0, b0a[2]), fmaf(w0a[3], x0, b0a[3]));
    pB01 = cvtpack(fmaf(w0b1[0], x2, fmaf(w0b0[0], x1, b0b[0])),
                   fmaf(w0b1[1], x2, fmaf(w0b0[1], x1, b0b[1])));
    pB23 = cvtpack(fmaf(w0b1[2], x2, fmaf(w0b0[2], x1, b0b[2])),
                   fmaf(w0b1[3], x2, fmaf(w0b0[3], x1, b0b[3])));

    float ucur = __ldg(&ue[0]);

    #pragma unroll 1
    for (int t = 0; t < TSEQ; t++) {
        // Emit pre-update state.
        if (g == 0)      ybase[t] = make_float2(x0, x1);
        else if (g == 1) xbase[t * 3 + 0] = x0;
        else if (g == 2) xbase[t * 3 + 1] = x1;
        else             xbase[t * 3 + 2] = x2;

        const float uc = fmaf(ku, ucur, kc);
        if (t + 1 < TSEQ) ucur = __ldg(&ue[t + 1]);

        __half2 p1h, p2h;
        float p1f, p2f, d0, d1, d2;
        unsigned bA01, bA23, bB01, bB23;

        // T1 base (c = x, gamma = 1/2), ready before stage-1 p arrives.
        mkBaseA(fmaf(0.5f, fmaf(-0.1f, x0, uc), x0), bA01, bA23);
        mkBaseB(fmaf(0.5f, fmaf(-0.1f, x1, kb), x1),
                fmaf(0.5f, fmaf(-0.1f, x2, kb), x2), bB01, bB23);

        // ---- stage 1 (k1) ----
        runStage(pA01, pA23, pB01, pB23, p1h, p2h);
        fastPath(0, p1h, p2h, bA01, bA23, bB01, bB23, pA01, pA23, pB01, pB23);
        p1f = __half2float(__low2half(p1h)); p2f = __half2float(__low2half(p2h));
        d0 = fmaf(-0.1f, x0, uc) - p1f;
        d1 = fmaf(kr, p1f, fmaf(-3.0f, p2f, fmaf(-0.1f, x1, kb)));
        d2 = fmaf(-0.1f, x2, kb) + p2f;
        float a0 = d0, a1 = d1, a2 = d2;
        float c20 = fmaf(0.5f, d0, x0), c21 = fmaf(0.5f, d1, x1), c22 = fmaf(0.5f, d2, x2);
        // T2 base (c = c2, gamma = 1/2)
        mkBaseA(fmaf(0.5f, fmaf(-0.1f, c20, uc), x0), bA01, bA23);
        mkBaseB(fmaf(0.5f, fmaf(-0.1f, c21, kb), x1),
                fmaf(0.5f, fmaf(-0.1f, c22, kb), x2), bB01, bB23);

        // ---- stage 2 (k2) ----
        runStage(pA01, pA23, pB01, pB23, p1h, p2h);
        fastPath(0, p1h, p2h, bA01, bA23, bB01, bB23, pA01, pA23, pB01, pB23);
        p1f = __half2float(__low2half(p1h)); p2f = __half2float(__low2half(p2h));
        d0 = fmaf(-0.1f, c20, uc) - p1f;
        d1 = fmaf(kr, p1f, fmaf(-3.0f, p2f, fmaf(-0.1f, c21, kb)));
        d2 = fmaf(-0.1f, c22, kb) + p2f;
        a0 = fmaf(2.0f, d0, a0); a1 = fmaf(2.0f, d1, a1); a2 = fmaf(2.0f, d2, a2);
        float c30 = fmaf(0.5f, d0, x0), c31 = fmaf(0.5f, d1, x1), c32 = fmaf(0.5f, d2, x2);
        // T3 base (c = c3, gamma = 1)
        mkBaseA(x0 + fmaf(-0.1f, c30, uc), bA01, bA23);
        mkBaseB(x1 + fmaf(-0.1f, c31, kb), x2 + fmaf(-0.1f, c32, kb), bB01, bB23);

        // ---- stage 3 (k3) ----
        runStage(pA01, pA23, pB01, pB23, p1h, p2h);
        fastPath(1, p1h, p2h, bA01, bA23, bB01, bB23, pA01, pA23, pB01, pB23);
        p1f = __half2float(__low2half(p1h)); p2f = __half2float(__low2half(p2h));
        d0 = fmaf(-0.1f, c30, uc) - p1f;
        d1 = fmaf(kr, p1f, fmaf(-3.0f, p2f, fmaf(-0.1f, c31, kb)));
        d2 = fmaf(-0.1f, c32, kb) + p2f;
        a0 = fmaf(2.0f, d0, a0); a1 = fmaf(2.0f, d1, a1); a2 = fmaf(2.0f, d2, a2);
        float c40 = x0 + d0, c41 = x1 + d1, c42 = x2 + d2;
        // T4 base (x_new path, gamma = 1/6): s = x + (a + d4_nop)/6
        const float c6 = 1.0f / 6.0f;
        mkBaseA(fmaf(c6, a0 + fmaf(-0.1f, c40, uc), x0), bA01, bA23);
        mkBaseB(fmaf(c6, a1 + fmaf(-0.1f, c41, kb), x1),
                fmaf(c6, a2 + fmaf(-0.1f, c42, kb), x2), bB01, bB23);

        // ---- stage 4 (k4) ----
        runStage(pA01, pA23, pB01, pB23, p1h, p2h);
        fastPath(2, p1h, p2h, bA01, bA23, bB01, bB23, pA01, pA23, pB01, pB23);
        p1f = __half2float(__low2half(p1h)); p2f = __half2float(__low2half(p2h));
        d0 = fmaf(-0.1f, c40, uc) - p1f;
        d1 = fmaf(kr, p1f, fmaf(-3.0f, p2f, fmaf(-0.1f, c41, kb)));
        d2 = fmaf(-0.1f, c42, kb) + p2f;
        x0 = fmaf(c6, a0 + d0, x0);
        x1 = fmaf(c6, a1 + d1, x1);
        x2 = fmaf(c6, a2 + d2, x2);
    }
}

extern "C" void kernel_launch(void* const* d_in, const int* in_sizes, int n_in,
                              void* d_out, int out_size) {
    (void)in_sizes; (void)n_in; (void)out_size;
    reac_kernel<<<128, 128>>>(
        (const float*)d_in[0],  (const float*)d_in[1],
        (const float*)d_in[2],  (const float*)d_in[3],
        (const float*)d_in[4],  (const float*)d_in[5],
        (const float*)d_in[6],  (const float*)d_in[7],
        (const float*)d_in[8],  (const float*)d_in[9],
        (const float*)d_in[10], (const float*)d_in[11],
        (const float*)d_in[12], (const float*)d_in[13],
        (const float*)d_in[14], (const float*)d_in[15],
        (const float*)d_in[16], (const float*)d_in[17],
        (float*)d_out);
}